// round 13
// baseline (speedup 1.0000x reference)
#include <cuda_runtime.h>

#define NHID 20
#define TPB  256
#define PPT  2
#define NJC  6                      // j-outputs served from constant (j 0..5)
#define NJS  (NHID - NJC)           // j-outputs served from smem (j 6..19)

typedef unsigned long long u64;

struct CParams {
    u64 Wc[6 * NHID * NJC];   // [l][k][j0..5] splat pairs (constant share)
    u64 B[6 * NHID];          // hidden biases, splats
    u64 W0[NHID];
    u64 B0[NHID];
    u64 W7[NHID];
    u64 B7;
};

__constant__ CParams cP;
__device__   CParams gStage;
__device__   u64     gSm[6 * NHID * NJS];   // [l][k][j6..19] splat pairs (smem share)

static __device__ __forceinline__ u64 pack2f(float lo, float hi) {
    u64 r;
    unsigned a = __float_as_uint(lo), b = __float_as_uint(hi);
    asm("mov.b64 %0, {%1, %2};" : "=l"(r) : "r"(a), "r"(b));
    return r;
}
static __device__ __forceinline__ void unpack2f(u64 v, float& lo, float& hi) {
    unsigned a, b;
    asm("mov.b64 {%0, %1}, %2;" : "=r"(a), "=r"(b) : "l"(v));
    lo = __uint_as_float(a);
    hi = __uint_as_float(b);
}
static __device__ __forceinline__ u64 fma2(u64 a, u64 b, u64 c) {
    u64 d;
    asm("fma.rn.f32x2 %0, %1, %2, %3;" : "=l"(d) : "l"(a), "l"(b), "l"(c));
    return d;
}
static __device__ __forceinline__ u64 mul2(u64 a, u64 b) {
    u64 d;
    asm("mul.rn.f32x2 %0, %1, %2;" : "=l"(d) : "l"(a), "l"(b));
    return d;
}
static __device__ __forceinline__ u64 add2(u64 a, u64 b) {
    u64 d;
    asm("add.rn.f32x2 %0, %1, %2;" : "=l"(d) : "l"(a), "l"(b));
    return d;
}
static __device__ __forceinline__ float ex2f(float x) {
    float r;
    asm("ex2.approx.f32 %0, %1;" : "=f"(r) : "f"(x));
    return r;
}
static __device__ __forceinline__ float rcpf(float x) {
    float r;
    asm("rcp.approx.f32 %0, %1;" : "=f"(r) : "f"(x));
    return r;
}

// silu pair: x * 1/(1+e^-x). 3 f32x2 fma-pipe ops + 4 MUFU.
static __device__ __forceinline__ u64 silu2(u64 x2, u64 negl2e2, u64 one2) {
    u64 m = mul2(x2, negl2e2);
    float mlo, mhi; unpack2f(m, mlo, mhi);
    u64 e = pack2f(ex2f(mlo), ex2f(mhi));
    u64 d = add2(e, one2);
    float dlo, dhi; unpack2f(d, dlo, dhi);
    u64 r = pack2f(rcpf(dlo), rcpf(dhi));
    return mul2(x2, r);
}

// Prep: build split transposed splat tables.
__global__ void prep_kernel(
    const float* __restrict__ W0, const float* __restrict__ b0,
    const float* __restrict__ W1, const float* __restrict__ b1,
    const float* __restrict__ W2, const float* __restrict__ b2,
    const float* __restrict__ W3, const float* __restrict__ b3,
    const float* __restrict__ W4, const float* __restrict__ b4,
    const float* __restrict__ W5, const float* __restrict__ b5,
    const float* __restrict__ W6, const float* __restrict__ b6,
    const float* __restrict__ W7, const float* __restrict__ b7)
{
    const int tid = blockIdx.x * blockDim.x + threadIdx.x;
    const int nthr = gridDim.x * blockDim.x;

    for (int i = tid; i < 6 * NHID * NHID; i += nthr) {
        int l = i / (NHID * NHID);
        int r = i - l * (NHID * NHID);
        int k = r / NHID;
        int j = r - k * NHID;
        int src = j * NHID + k;          // row-major W[j][k]
        float w;
        switch (l) {
            case 0: w = W1[src]; break;
            case 1: w = W2[src]; break;
            case 2: w = W3[src]; break;
            case 3: w = W4[src]; break;
            case 4: w = W5[src]; break;
            default: w = W6[src]; break;
        }
        u64 p = pack2f(w, w);
        if (j < NJC)
            gStage.Wc[(l * NHID + k) * NJC + j] = p;
        else
            gSm[(l * NHID + k) * NJS + (j - NJC)] = p;
    }
    for (int i = tid; i < 6 * NHID; i += nthr) {
        int l = i / NHID;
        int r = i - l * NHID;
        float w;
        switch (l) {
            case 0: w = b1[r]; break;
            case 1: w = b2[r]; break;
            case 2: w = b3[r]; break;
            case 3: w = b4[r]; break;
            case 4: w = b5[r]; break;
            default: w = b6[r]; break;
        }
        gStage.B[i] = pack2f(w, w);
    }
    for (int i = tid; i < NHID; i += nthr) {
        gStage.W0[i] = pack2f(W0[i], W0[i]);
        gStage.B0[i] = pack2f(b0[i], b0[i]);
        gStage.W7[i] = pack2f(W7[i], W7[i]);
    }
    if (tid == 0) gStage.B7 = pack2f(b7[0], b7[0]);
}

__global__ void __launch_bounds__(TPB, 2)   // 128 regs -> 4 warps/SMSP
SpringEquationNN_kernel(const float* __restrict__ t,
                        float* __restrict__ out, int n)
{
    // smem share of the weights: [l][k][j6..19], 16B-aligned rows (NJS=14 even).
    __shared__ __align__(16) u64 sW[6 * NHID * NJS];

    const int tid = threadIdx.x;
    for (int i = tid; i < 6 * NHID * NJS; i += TPB)
        sW[i] = gSm[i];
    __syncthreads();

    const u64 NEGL2E2 = pack2f(-1.442695041f, -1.442695041f);
    const u64 ONE2    = pack2f(1.0f, 1.0f);

    const int base = (blockIdx.x * TPB + tid) * PPT;
    if (base >= n) return;

    float tx, ty;
    if (base + 2 <= n) {
        float2 v = *reinterpret_cast<const float2*>(t + base);
        tx = v.x; ty = v.y;
    } else {
        tx = t[base]; ty = 0.0f;
    }
    const u64 x0 = pack2f(tx, ty);

    u64 h[NHID];

    // Layer 0: 1 -> 20 (constant, immediate offsets)
    #pragma unroll
    for (int j = 0; j < NHID; j++)
        h[j] = silu2(fma2(x0, cP.W0[j], cP.B0[j]), NEGL2E2, ONE2);

    // Hidden layers: k-outer register accumulation, weights split across
    // the constant port (j 0..5) and the shared crossbar (j 6..19).
    for (int l = 0; l < 6; l++) {
        const ulonglong2* wc =
            reinterpret_cast<const ulonglong2*>(cP.Wc + l * NHID * NJC);
        const ulonglong2* ws =
            reinterpret_cast<const ulonglong2*>(sW + l * NHID * NJS);
        const ulonglong2* bl =
            reinterpret_cast<const ulonglong2*>(cP.B + l * NHID);

        u64 acc[NHID];
        #pragma unroll
        for (int j2 = 0; j2 < NHID / 2; j2++) {
            ulonglong2 bb = bl[j2];
            acc[2 * j2]     = bb.x;
            acc[2 * j2 + 1] = bb.y;
        }

        #pragma unroll
        for (int k = 0; k < NHID; k++) {
            const u64 hk = h[k];
            // constant share: j = 0..5  (3x LDC.128)
            #pragma unroll
            for (int j2 = 0; j2 < NJC / 2; j2++) {
                ulonglong2 w = wc[k * (NJC / 2) + j2];
                acc[2 * j2]     = fma2(hk, w.x, acc[2 * j2]);
                acc[2 * j2 + 1] = fma2(hk, w.y, acc[2 * j2 + 1]);
            }
            // smem share: j = 6..19  (7x LDS.128 broadcast)
            #pragma unroll
            for (int j2 = 0; j2 < NJS / 2; j2++) {
                ulonglong2 w = ws[k * (NJS / 2) + j2];
                acc[NJC + 2 * j2]     = fma2(hk, w.x, acc[NJC + 2 * j2]);
                acc[NJC + 2 * j2 + 1] = fma2(hk, w.y, acc[NJC + 2 * j2 + 1]);
            }
        }

        #pragma unroll
        for (int j = 0; j < NHID; j++)
            h[j] = silu2(acc[j], NEGL2E2, ONE2);
    }

    // Output layer: 20 -> 1 (constant, dual chains)
    {
        const ulonglong2* w7 = reinterpret_cast<const ulonglong2*>(cP.W7);
        u64 accE = cP.B7;
        u64 accO = 0ull;
        #pragma unroll
        for (int k2 = 0; k2 < NHID / 2; k2++) {
            ulonglong2 w = w7[k2];
            accE = fma2(h[2 * k2],     w.x, accE);
            accO = fma2(h[2 * k2 + 1], w.y, accO);
        }
        u64 a = add2(accE, accO);
        float o0, o1;
        unpack2f(a, o0, o1);
        if (base + 2 <= n) {
            *reinterpret_cast<float2*>(out + base) = make_float2(o0, o1);
        } else {
            out[base] = o0;
        }
    }
}

extern "C" void kernel_launch(void* const* d_in, const int* in_sizes, int n_in,
                              void* d_out, int out_size)
{
    const float* t  = (const float*)d_in[0];
    const float* W0 = (const float*)d_in[1];
    const float* b0 = (const float*)d_in[2];
    const float* W1 = (const float*)d_in[3];
    const float* b1 = (const float*)d_in[4];
    const float* W2 = (const float*)d_in[5];
    const float* b2 = (const float*)d_in[6];
    const float* W3 = (const float*)d_in[7];
    const float* b3 = (const float*)d_in[8];
    const float* W4 = (const float*)d_in[9];
    const float* b4 = (const float*)d_in[10];
    const float* W5 = (const float*)d_in[11];
    const float* b5 = (const float*)d_in[12];
    const float* W6 = (const float*)d_in[13];
    const float* b6 = (const float*)d_in[14];
    const float* W7 = (const float*)d_in[15];
    const float* b7 = (const float*)d_in[16];

    const int n = in_sizes[0];
    float* out = (float*)d_out;

    // 1) Build split splat tables (const share + smem share).
    prep_kernel<<<4, 256>>>(W0, b0, W1, b1, W2, b2, W3, b3,
                            W4, b4, W5, b5, W6, b6, W7, b7);

    // 2) Stage -> constant aperture (graph-capturable D2D memcpy).
    void* cAddr = nullptr;
    void* gAddr = nullptr;
    cudaGetSymbolAddress(&cAddr, cP);
    cudaGetSymbolAddress(&gAddr, gStage);
    cudaMemcpyAsync(cAddr, gAddr, sizeof(CParams), cudaMemcpyDeviceToDevice);

    // 3) Main evaluation.
    const int pts_per_block = TPB * PPT;
    const int grid = (n + pts_per_block - 1) / pts_per_block;
    SpringEquationNN_kernel<<<grid, TPB>>>(t, out, n);
}